// round 8
// baseline (speedup 1.0000x reference)
#include <cuda_runtime.h>
#include <cstdint>

typedef unsigned long long u64;

#define NB 16
#define NF 20
#define NT 128
#define ND 300
#define NH 256
#define NG 1024   // 4*H
#define SEQS 320  // NB*NF
#define NM 40960  // SEQS*NT

// Scratch: projection output 335 MB, U repack 2 MB, mask 40 KB, h slabs 640 KB.
__device__ float g_xz[2ull * NM * NG];
// U for lstm: [d][c 8][k 256][gi 2][p 64] f32;
//   gcol = (p<32 ? 0 : 512) + gi*256 + c*32 + (p&31)
__device__ float g_U8[2 * 8 * 256 * 128];
__device__ unsigned char g_mask[SEQS * NT];
// h exchange slabs: [d][grp 8][k2 128][sp 20][kk 2][lo/hi 2] f32 (= 40 KB per cluster)
__device__ float g_hx[2 * 8 * 10240];

__device__ __forceinline__ u64 pack2(float a, float b){
    u64 r; asm("mov.b64 %0, {%1, %2};" : "=l"(r) : "f"(a), "f"(b)); return r;
}
__device__ __forceinline__ u64 ffma2(u64 a, u64 b, u64 c){
    u64 d; asm("fma.rn.f32x2 %0, %1, %2, %3;" : "=l"(d) : "l"(a), "l"(b), "l"(c)); return d;
}
__device__ __forceinline__ uint32_t smem_u32(const void* p){
    uint32_t a; asm("{ .reg .u64 t; cvta.to.shared.u64 t, %1; cvt.u32.u64 %0, t; }" : "=r"(a) : "l"(p));
    return a;
}
__device__ __forceinline__ void cluster_sync(){
    asm volatile("barrier.cluster.arrive.aligned;\n\tbarrier.cluster.wait.aligned;" ::: "memory");
}
__device__ __forceinline__ void cp_async16(uint32_t sdst, const void* gsrc){
    asm volatile("cp.async.ca.shared.global [%0], [%1], 16;" :: "r"(sdst), "l"(gsrc) : "memory");
}
__device__ __forceinline__ void cp_async_commit(){
    asm volatile("cp.async.commit_group;" ::: "memory");
}
__device__ __forceinline__ void cp_async_wait0(){
    asm volatile("cp.async.wait_group 0;" ::: "memory");
}

// ---------------------------------------------------------------------------
// Repack U into the per-cluster-CTA smem image layout (see g_U8 comment).
// ---------------------------------------------------------------------------
__global__ void repack_u_kernel(const float* __restrict__ Uf, const float* __restrict__ Ub)
{
    int idx = blockIdx.x * 256 + threadIdx.x;   // 0 .. 524287
    int p  = idx & 63;
    int gi = (idx >> 6) & 1;
    int k  = (idx >> 7) & 255;
    int c  = (idx >> 15) & 7;
    int d  = idx >> 18;
    const float* U = d ? Ub : Uf;
    int gcol = ((p < 32) ? 0 : 512) + gi * 256 + c * 32 + (p & 31);
    g_U8[idx] = U[(size_t)k * NG + gcol];
}

// ---------------------------------------------------------------------------
// Canonicalize mask to u8. mask[0][0], mask[0][1] guaranteed true (len >= 64):
// byte0==0 -> float32; byte1!=0 -> uint8; else -> int32.
// ---------------------------------------------------------------------------
__global__ void repack_mask_kernel(const unsigned char* __restrict__ raw)
{
    int idx = blockIdx.x * 256 + threadIdx.x;
    unsigned char b0 = raw[0], b1 = raw[1];
    unsigned char v;
    if (b0 == 0)      v = (((const float*)raw)[idx] != 0.0f);
    else if (b1 != 0) v = (raw[idx] != 0);
    else              v = (((const int*)raw)[idx] != 0);
    g_mask[idx] = v;
}

// ---------------------------------------------------------------------------
// Phase 1: xz = x @ W + b.  M=40960, K=300, N=1024 per dir. (unchanged)
// ---------------------------------------------------------------------------
#define BM 128
#define BN 128
#define BK 20
#define KT 300

__global__ __launch_bounds__(256, 2) void proj_kernel(
    const float* __restrict__ x,
    const float* __restrict__ Wf, const float* __restrict__ bf,
    const float* __restrict__ Wb, const float* __restrict__ bb)
{
    __shared__ u64  Asd[BK][BM + 2];
    __shared__ float Bs[BK][BN];

    const int tid = threadIdx.x;
    const int m0  = blockIdx.x * BM;
    const int d   = blockIdx.y >> 3;
    const int n0  = (blockIdx.y & 7) * BN;
    const float* __restrict__ W    = d ? Wb : Wf;
    const float* __restrict__ bias = d ? bb : bf;
    const int tc = tid & 15;
    const int tr = tid >> 4;

    u64 acc[8][4];
    {
        const float* bp = bias + n0 + tc * 8;
        u64 b0 = pack2(bp[0], bp[1]);
        u64 b1 = pack2(bp[2], bp[3]);
        u64 b2 = pack2(bp[4], bp[5]);
        u64 b3 = pack2(bp[6], bp[7]);
        #pragma unroll
        for (int i = 0; i < 8; i++){ acc[i][0]=b0; acc[i][1]=b1; acc[i][2]=b2; acc[i][3]=b3; }
    }

    for (int kt = 0; kt < KT; kt += BK){
        #pragma unroll
        for (int i = 0; i < 10; i++){
            int li = tid + i * 256;
            int m  = li / BK;
            int k  = li % BK;
            float v = x[(size_t)(m0 + m) * ND + kt + k];
            Asd[k][m] = pack2(v, v);
        }
        #pragma unroll
        for (int i = 0; i < 10; i++){
            int li = tid + i * 256;
            int k  = li >> 7;
            int n  = li & 127;
            Bs[k][n] = W[(size_t)(kt + k) * NG + n0 + n];
        }
        __syncthreads();

        #pragma unroll
        for (int k = 0; k < BK; k++){
            u64 a[8];
            {
                const ulonglong2* ap = (const ulonglong2*)&Asd[k][tr * 8];
                ulonglong2 a01 = ap[0], a23 = ap[1], a45 = ap[2], a67 = ap[3];
                a[0]=a01.x; a[1]=a01.y; a[2]=a23.x; a[3]=a23.y;
                a[4]=a45.x; a[5]=a45.y; a[6]=a67.x; a[7]=a67.y;
            }
            u64 b[4];
            {
                const ulonglong2* bp = (const ulonglong2*)&Bs[k][tc * 8];
                ulonglong2 b01 = bp[0], b23 = bp[1];
                b[0]=b01.x; b[1]=b01.y; b[2]=b23.x; b[3]=b23.y;
            }
            #pragma unroll
            for (int i = 0; i < 8; i++){
                #pragma unroll
                for (int j = 0; j < 4; j++){
                    acc[i][j] = ffma2(a[i], b[j], acc[i][j]);
                }
            }
        }
        __syncthreads();
    }

    #pragma unroll
    for (int i = 0; i < 8; i++){
        size_t row = (size_t)d * NM + (size_t)(m0 + tr * 8 + i);
        ulonglong2* orow = (ulonglong2*)(g_xz + row * NG + n0 + tc * 8);
        ulonglong2 v0; v0.x = acc[i][0]; v0.y = acc[i][1];
        ulonglong2 v1; v1.x = acc[i][2]; v1.y = acc[i][3];
        orow[0] = v0; orow[1] = v1;
    }
}

// ---------------------------------------------------------------------------
// Phase 2: LSTM recurrence, 8-CTA clusters (16 clusters), 40 seqs/cluster,
// U resident in smem for all 128 steps. 256 threads/CTA.
// k-loop role (p 0..63, sg 0..3): 2 gate-cols (pair-col p: p<32 -> (i,f) of
//   j=p; p>=32 -> (g,o) of j=p-32), 10 seqs as 5 (s,s+1) f32x2 pairs, full
//   k=256. Per k2: 4 LDS.32 U + 4 packs + 5 LDS.128 h + 20 FFMA2.
// Finalize role (jj 0..31, sb 0..7): hidden j = c*32+jj, seqs 5*sb..+4.
//   Sums exch+xz, gates, writes h to cluster slab in L2; cp.async readback.
// smem: U 131072 + h 40960 + exch 21504 + xz 20480 + mask 5120 = 219136 B.
// ---------------------------------------------------------------------------
#define SM_U  0
#define SM_H  131072
#define SM_EX (SM_H + 40960)
#define SM_XZ (SM_EX + 21504)
#define SM_MK (SM_XZ + 20480)
#define LSTM_SMEM (SM_MK + 5120)

__global__ __launch_bounds__(256, 1) __cluster_dims__(8, 1, 1)
void lstm_kernel(float* __restrict__ out)
{
    extern __shared__ __align__(16) char dsm[];
    float* shU = (float*)(dsm + SM_U);     // [k 256][gi 2][p 64] f32
    u64*   shH = (u64*)(dsm + SM_H);       // [k2 128][sp 20][kk 2] u64 (s,s+1 pairs)
    float* shE = (float*)(dsm + SM_EX);    // [p2 128][42] f32 (rows padded 40->42)
    float* shX = (float*)(dsm + SM_XZ);    // [g 4][s 40][jj 32] f32
    unsigned char* shM = (unsigned char*)(dsm + SM_MK);  // [s 40][t 128]

    const int tid = threadIdx.x;
    const int c   = blockIdx.x;            // cluster rank (8 CTAs)
    const int grp = blockIdx.y;            // 8 groups per dir
    const int d   = blockIdx.z;
    const int seq0 = grp * 40;

    // k-loop role
    const int p  = tid & 63;
    const int sg = tid >> 6;
    // finalize role
    const int jj = tid & 31;
    const int sb = tid >> 5;
    const int s0 = sb * 5;
    const int jg = c * 32 + jj;

    // Load U slice into smem (resident for all steps).
    {
        const float* src = g_U8 + (size_t)(d * 8 + c) * 256 * 128;
        uint32_t u32 = smem_u32(shU);
        for (int i = tid; i < 8192; i += 256)
            cp_async16(u32 + i * 16, src + i * 4);
        cp_async_commit();
    }
    // Mask for this cluster's 40 seqs; zero h.
    for (int i = tid; i < 5120; i += 256)
        shM[i] = g_mask[seq0 * NT + i];
    for (int i = tid; i < 5120; i += 256)      // 128*20*2 u64
        shH[i] = 0ull;
    cp_async_wait0();
    __syncthreads();

    float c_st[5];
    #pragma unroll
    for (int i = 0; i < 5; i++) c_st[i] = 0.f;

    const float* xzb = g_xz + (size_t)d * NM * NG + (size_t)seq0 * NT * NG;
    float* hx = g_hx + (size_t)(d * 8 + grp) * 10240;
    const uint32_t xz32 = smem_u32(shX);
    const uint32_t h32  = smem_u32(shH);
    u64* ex64 = (u64*)shE;

    for (int step = 0; step < NT; ++step){
        const int t = d ? (NT - 1 - step) : step;

        // Stage xz[t] (read at finalize, ~10K cycles from now).
        #pragma unroll
        for (int i = tid; i < 1280; i += 256){
            int g  = i / 320;
            int r  = i % 320;
            int s  = r >> 3;
            int ch = r & 7;
            const float* src = xzb + ((size_t)s * NT + t) * NG + g * 256 + c * 32 + ch * 4;
            cp_async16(xz32 + (uint32_t)(((g * 40 + s) * 32 + ch * 4) * 4), src);
        }
        cp_async_commit();

        // Main k-loop: 128 k2 iterations over smem-resident U and h.
        u64 acc[2][5];
        #pragma unroll
        for (int gi = 0; gi < 2; gi++)
            #pragma unroll
            for (int sp = 0; sp < 5; sp++) acc[gi][sp] = 0ull;

        #pragma unroll 4
        for (int k2 = 0; k2 < 128; k2++){
            const float* u0 = shU + k2 * 256;
            float ua = u0[p], ub = u0[64 + p];          // k=2k2:   gi0, gi1
            float uc = u0[128 + p], ud = u0[192 + p];   // k=2k2+1: gi0, gi1
            u64 ua2 = pack2(ua, ua), ub2 = pack2(ub, ub);
            u64 uc2 = pack2(uc, uc), ud2 = pack2(ud, ud);
            const ulonglong2* hp = (const ulonglong2*)(shH + (k2 * 20 + 5 * sg) * 2);
            ulonglong2 h0 = hp[0], h1 = hp[1], h2 = hp[2], h3 = hp[3], h4 = hp[4];
            u64 hk0[5] = { h0.x, h1.x, h2.x, h3.x, h4.x };   // k even, sp 0..4
            u64 hk1[5] = { h0.y, h1.y, h2.y, h3.y, h4.y };   // k odd
            #pragma unroll
            for (int sp = 0; sp < 5; sp++){
                acc[0][sp] = ffma2(hk0[sp], ua2, acc[0][sp]);
                acc[1][sp] = ffma2(hk0[sp], ub2, acc[1][sp]);
                acc[0][sp] = ffma2(hk1[sp], uc2, acc[0][sp]);
                acc[1][sp] = ffma2(hk1[sp], ud2, acc[1][sp]);
            }
        }

        // Exchange partials: shE[p2][42] f32, u64 row stride 21.
        #pragma unroll
        for (int gi = 0; gi < 2; gi++)
            #pragma unroll
            for (int sp = 0; sp < 5; sp++)
                ex64[(p * 2 + gi) * 21 + 5 * sg + sp] = acc[gi][sp];
        cp_async_wait0();       // xz[t] complete
        __syncthreads();

        // Finalize: j = jg, seqs s0..s0+4.
        #pragma unroll
        for (int si = 0; si < 5; si++){
            const int s = s0 + si;
            float zi = shE[(jj * 2 + 0) * 42 + s]        + shX[(0 * 40 + s) * 32 + jj];
            float zf = shE[(jj * 2 + 1) * 42 + s]        + shX[(1 * 40 + s) * 32 + jj];
            float zg = shE[((32 + jj) * 2 + 0) * 42 + s] + shX[(2 * 40 + s) * 32 + jj];
            float zo = shE[((32 + jj) * 2 + 1) * 42 + s] + shX[(3 * 40 + s) * 32 + jj];
            float ig = __fdividef(1.f, 1.f + __expf(-zi));
            float fg = __fdividef(1.f, 1.f + __expf(-zf));
            float gg = 1.f - __fdividef(2.f, __expf(2.f * zg) + 1.f);
            float og = 1.f - __fdividef(1.f, 1.f + __expf(zo));
            float cn = fg * c_st[si] + ig * gg;
            float hn = og * (1.f - __fdividef(2.f, __expf(2.f * cn) + 1.f));
            const int hidx = (jg >> 1) * 80 + (s >> 1) * 4 + (jg & 1) * 2 + (s & 1);
            float hprev = ((const float*)shH)[hidx];
            bool m = shM[s * NT + t] != 0;
            float hnew = m ? hn : hprev;
            if (m) c_st[si] = cn;
            hx[hidx] = hnew;
            out[((size_t)(seq0 + s) * NT + t) * (2 * NH) + d * NH + jg] = hnew;
        }
        asm volatile("membar.gl;" ::: "memory");
        cluster_sync();

        // Read back full cluster h (40 KB) into smem.
        #pragma unroll
        for (int i = 0; i < 10; i++){
            int o = tid + i * 256;    // 2560 16B chunks
            cp_async16(h32 + o * 16, hx + o * 4);
        }
        cp_async_commit();
        cp_async_wait0();
        __syncthreads();
    }
}

extern "C" void kernel_launch(void* const* d_in, const int* in_sizes, int n_in,
                              void* d_out, int out_size)
{
    const float*         facts = (const float*)d_in[0];
    const unsigned char* mask  = (const unsigned char*)d_in[1];
    const float*         Wf    = (const float*)d_in[2];
    const float*         Uf    = (const float*)d_in[3];
    const float*         bf    = (const float*)d_in[4];
    const float*         Wb    = (const float*)d_in[5];
    const float*         Ub    = (const float*)d_in[6];
    const float*         bb    = (const float*)d_in[7];
    float* out = (float*)d_out;

    cudaFuncSetAttribute(lstm_kernel, cudaFuncAttributeMaxDynamicSharedMemorySize, LSTM_SMEM);

    repack_u_kernel<<<2048, 256>>>(Uf, Ub);
    repack_mask_kernel<<<SEQS * NT / 256, 256>>>(mask);
    proj_kernel<<<dim3(NM / BM, 16), 256>>>(facts, Wf, bf, Wb, bb);
    lstm_kernel<<<dim3(8, 8, 2), 256, LSTM_SMEM>>>(out);
}